// round 1
// baseline (speedup 1.0000x reference)
#include <cuda_runtime.h>
#include <cuda_bf16.h>

// DiagPooling: x [B=8, C=128, H=512, W=512] fp32 -> out [B, 1, 513] fp32
// out[b, 0, o] = mean over (c, diagonal) of x[b, c, i, i + (o-256)]
//             = (1 / (C * (H - |o-256|))) * sum_{c, i} x[b, c, i, i + o - 256]

#define B_DIM 8
#define C_DIM 128
#define H_DIM 512
#define W_DIM 512
#define N_OFF 513   // offsets -256..256
#define OUT_ELEMS (B_DIM * N_OFF)

__global__ void zero_out_kernel(float* __restrict__ out, int n) {
    int idx = blockIdx.x * blockDim.x + threadIdx.x;
    if (idx < n) out[idx] = 0.0f;
}

__global__ __launch_bounds__(512) void diag_pool_kernel(
    const float* __restrict__ x, float* __restrict__ out)
{
    const int i = blockIdx.x;   // row 0..511
    const int b = blockIdx.y;   // batch 0..7
    const int t = threadIdx.x;  // 0..511

    // Valid column range for this row: |j - i| <= 256
    const int j0 = (i - 256 > 0) ? (i - 256) : 0;
    const int j1 = (i + 256 < H_DIM - 1) ? (i + 256) : (H_DIM - 1);
    const int j = j0 + t;
    if (j > j1) return;

    // Base pointer: x[b, 0, i, j]; channel stride = H*W elements
    const size_t ch_stride = (size_t)H_DIM * W_DIM;
    const float* p = x + ((size_t)b * C_DIM * H_DIM + (size_t)i) * W_DIM + j;

    // Sum over all 128 channels with 4 independent accumulators
    float s0 = 0.f, s1 = 0.f, s2 = 0.f, s3 = 0.f;
    #pragma unroll 8
    for (int c = 0; c < C_DIM; c += 4) {
        s0 += __ldg(p + (size_t)(c + 0) * ch_stride);
        s1 += __ldg(p + (size_t)(c + 1) * ch_stride);
        s2 += __ldg(p + (size_t)(c + 2) * ch_stride);
        s3 += __ldg(p + (size_t)(c + 3) * ch_stride);
    }
    float s = (s0 + s1) + (s2 + s3);

    // Diagonal/output index and normalization
    const int o = j - i + 256;                 // 0..512, unique within block
    const int off = o - 256;
    const int diag_len = H_DIM - (off < 0 ? -off : off);
    const float denom = (float)(C_DIM) * (float)diag_len;

    atomicAdd(&out[b * N_OFF + o], s / denom);
}

extern "C" void kernel_launch(void* const* d_in, const int* in_sizes, int n_in,
                              void* d_out, int out_size) {
    const float* x = (const float*)d_in[0];
    float* out = (float*)d_out;

    zero_out_kernel<<<(OUT_ELEMS + 255) / 256, 256>>>(out, OUT_ELEMS);

    dim3 grid(H_DIM, B_DIM);
    diag_pool_kernel<<<grid, 512>>>(x, out);
}